// round 9
// baseline (speedup 1.0000x reference)
#include <cuda_runtime.h>
#include <stdint.h>
#include <math.h>

#define DD   20
#define TPB  128
#define WPB  4               // warps per block
#define NCTA 760             // 152 SMs x 5 CTAs
#define HST  20              // h smem row stride (floats): conflict-free reloads

__device__ double   g_psum[NCTA];
__device__ double   g_pabs[NCTA];
__device__ unsigned g_done = 0;

static __device__ __forceinline__ uint32_t f2tf(float f) {   // exact rna (prologue only)
    uint32_t u; asm("cvt.rna.tf32.f32 %0, %1;" : "=r"(u) : "f"(f)); return u;
}
// rna-to-tf32 via mantissa carry: HW keeps bits [31:13]; +0x1000 rounds half-away.
static __device__ __forceinline__ uint32_t rna(float f) {
    return __float_as_uint(f) + 0x1000u;
}
static __device__ __forceinline__ void mma8(float* c, const uint32_t* a, const uint32_t* b) {
    asm volatile("mma.sync.aligned.m16n8k8.row.col.f32.tf32.tf32.f32 "
        "{%0,%1,%2,%3}, {%4,%5,%6,%7}, {%8,%9}, {%0,%1,%2,%3};"
        : "+f"(c[0]), "+f"(c[1]), "+f"(c[2]), "+f"(c[3])
        : "r"(a[0]), "r"(a[1]), "r"(a[2]), "r"(a[3]), "r"(b[0]), "r"(b[1]));
}
static __device__ __forceinline__ uint32_t s2u(const void* p) {
    uint32_t a;
    asm("{ .reg .u64 t; cvta.to.shared.u64 t, %1; cvt.u32.u64 %0, t; }" : "=r"(a) : "l"(p));
    return a;
}
// per-warp tile prefetch: 2560B = 5 coalesced 16B cp.async per lane
static __device__ __forceinline__ void issue_tile(const char* Xb, long long tile,
                                                  long long ntiles, long long maxoff,
                                                  uint32_t dst, int lane) {
    if (tile >= ntiles) tile = ntiles - 1;
    long long base = tile * 2560 + (long long)lane * 16;
    #pragma unroll
    for (int c = 0; c < 5; c++) {
        long long off = base + c * 512;
        if (off > maxoff) off = maxoff;
        asm volatile("cp.async.cg.shared.global [%0], [%1], 16;"
                     :: "r"(dst + c * 512 + lane * 16), "l"(Xb + off) : "memory");
    }
    asm volatile("cp.async.commit_group;" ::: "memory");
}

__global__ void __launch_bounds__(TPB, 5)
fused_kernel(const float* __restrict__ X, const float* __restrict__ W,
             const float* __restrict__ bvec, const float* __restrict__ Wi,
             long long nrows, float* __restrict__ out) {
    // h-roundtrip arena; prologue weight arrays overlay it (disjoint lifetimes)
    __shared__ __align__(16) char arena[WPB * 2 * 16 * HST * 4];        // 10240B
    // X triple buffer; final fs/fa overlay it
    __shared__ __align__(16) float sXb[WPB * 3 * 32 * DD];              // 30720B
    __shared__ double s_rs[WPB], s_ra[WPB];
    __shared__ int    s_last;

    const int t = threadIdx.x;
    const int wid = t >> 5, lane = t & 31;
    const int qr = lane >> 2, qc = lane & 3;

    // ---- prologue (arena overlay): M1 = W^T@Wi, c1 = b@Wi + 1 ----
    {
        float* sW  = (float*)arena;          // 400
        float* sWi = sW + 400;               // 400
        float* sM1 = sWi + 400;              // 400
        float* sc1 = sM1 + 400;              // 20
        float* sb2 = sc1 + 20;               // 20   (total 4960B <= 10240B)

        for (int i = t; i < 400; i += TPB) { sW[i] = W[i]; sWi[i] = Wi[i]; }
        if (t < DD) sb2[t] = bvec[t];
        __syncthreads();
        for (int e = t; e < 400; e += TPB) {
            int k = e / 20, n = e % 20;
            float a = 0.f;
            #pragma unroll
            for (int j = 0; j < 20; j++) a = fmaf(sW[j*20 + k], sWi[j*20 + n], a);
            sM1[e] = a;
        }
        if (t < DD) {
            float a = 1.f;
            #pragma unroll
            for (int j = 0; j < 20; j++) a = fmaf(sb2[j], sWi[j*20 + t], a);
            sc1[t] = a;
        }
        __syncthreads();
    }

    // ---- constant B fragments (exact rna) + bias C-inits, in regs ----
    uint32_t b1f[3][3][2], b2f[3][3][2];
    float    bi1[3][2], bi2[3][2];
    {
        float* sW  = (float*)arena;
        float* sM1 = sW + 800;
        float* sc1 = sM1 + 400;
        float* sb2 = sc1 + 20;
        #pragma unroll
        for (int j = 0; j < 3; j++) {
            int k0 = 8*j + qc, k1 = k0 + 4;
            #pragma unroll
            for (int i = 0; i < 3; i++) {
                int n = 8*i + qr;
                float v0 = (k0 < 20 && n < 20) ? sM1[k0*20 + n] : 0.f;
                float v1 = (k1 < 20 && n < 20) ? sM1[k1*20 + n] : 0.f;
                b1f[j][i][0] = f2tf(v0); b1f[j][i][1] = f2tf(v1);
                float w0 = (k0 < 20 && n < 20) ? sW[n*20 + k0] : 0.f;
                float w1 = (k1 < 20 && n < 20) ? sW[n*20 + k1] : 0.f;
                b2f[j][i][0] = f2tf(w0); b2f[j][i][1] = f2tf(w1);
            }
        }
        #pragma unroll
        for (int i = 0; i < 3; i++) {
            int n0 = 8*i + 2*qc;
            bi1[i][0] = (n0     < 20) ? sc1[n0]     : 0.f;
            bi1[i][1] = (n0 + 1 < 20) ? sc1[n0 + 1] : 0.f;
            bi2[i][0] = (n0     < 20) ? sb2[n0]     : 0.f;
            bi2[i][1] = (n0 + 1 < 20) ? sb2[n0 + 1] : 0.f;
        }
        __syncthreads();   // prologue reads done before arena reused for h
    }

    // ---- mainloop: 32 rows/warp/iter, depth-3 cp.async pipeline ----
    const long long ntiles = (nrows + 31) >> 5;
    const long long gw = (long long)blockIdx.x * WPB + wid;
    const long long nw = (long long)gridDim.x * WPB;
    const long long maxoff = nrows * 80 - 16;
    const char* Xb = (const char*)X;

    float* px0 = sXb + wid * (3 * 32 * DD);
    float* px1 = px0 + 32 * DD;
    float* px2 = px1 + 32 * DD;
    uint32_t dA = s2u(px0), dB = s2u(px1), dC = s2u(px2);
    const float *fA = px0, *fB = px1, *fC = px2;

    float aS0 = 0.f, aS1 = 0.f, aA0 = 0.f, aA1 = 0.f;

    issue_tile(Xb, gw,      ntiles, maxoff, dA, lane);
    issue_tile(Xb, gw + nw, ntiles, maxoff, dB, lane);

    for (long long tl = gw; tl < ntiles; tl += nw) {
        issue_tile(Xb, tl + 2*nw, ntiles, maxoff, dC, lane);
        asm volatile("cp.async.wait_group 2;" ::: "memory");
        __syncwarp();

        const float* xs = fA;
        const long long Rt = tl << 5;

        // ---- A fragments: rna via IADD (HW truncates low 13 bits) ----
        uint32_t a[2][3][4];
        #pragma unroll
        for (int s = 0; s < 2; s++) {
            const float* q0 = xs + (s*16 + qr) * 20;
            const float* q1 = q0 + 8 * 20;
            #pragma unroll
            for (int j = 0; j < 2; j++) {
                a[s][j][0] = rna(q0[8*j + qc]);
                a[s][j][1] = rna(q1[8*j + qc]);
                a[s][j][2] = rna(q0[8*j + qc + 4]);
                a[s][j][3] = rna(q1[8*j + qc + 4]);
            }
            a[s][2][0] = rna(q0[16 + qc]);
            a[s][2][1] = rna(q1[16 + qc]);
            a[s][2][2] = 0u;
            a[s][2][3] = 0u;
        }

        // ---- stage 1: h = relu(X @ M1 + c1) -> per-warp smem ----
        // cols 20..23 are N-padding: with HST=20 they'd alias the next row,
        // so the i=2 stores are predicated to qc<2 (cols 16,18 only).
        #pragma unroll
        for (int s = 0; s < 2; s++) {
            float* hw = (float*)arena + wid * (2 * 16 * HST) + s * (16 * HST);
            #pragma unroll
            for (int i = 0; i < 3; i++) {
                float c[4] = { bi1[i][0], bi1[i][1], bi1[i][0], bi1[i][1] };
                mma8(c, a[s][0], b1f[0][i]);
                mma8(c, a[s][1], b1f[1][i]);
                mma8(c, a[s][2], b1f[2][i]);
                int col = 8*i + 2*qc;
                if (col < 20) {
                    float2 v0 = make_float2(fmaxf(c[0], 0.f), fmaxf(c[1], 0.f));
                    float2 v1 = make_float2(fmaxf(c[2], 0.f), fmaxf(c[3], 0.f));
                    *(float2*)&hw[qr*HST + col]       = v0;
                    *(float2*)&hw[(qr + 8)*HST + col] = v1;
                }
            }
        }
        __syncwarp();

        // ---- layout conversion: h -> A fragments (rna via IADD) ----
        uint32_t a2[2][3][4];
        #pragma unroll
        for (int s = 0; s < 2; s++) {
            const float* hw = (const float*)arena + wid * (2 * 16 * HST) + s * (16 * HST);
            #pragma unroll
            for (int j = 0; j < 3; j++) {
                a2[s][j][0] = rna(hw[qr*HST + 8*j + qc]);
                a2[s][j][1] = rna(hw[(qr + 8)*HST + 8*j + qc]);
                a2[s][j][2] = rna(hw[qr*HST + 8*j + qc + 4]);
                a2[s][j][3] = rna(hw[(qr + 8)*HST + 8*j + qc + 4]);
            }
        }
        __syncwarp();

        // ---- stage 2: h3 = h @ W^T + b; split accumulator chains ----
        #pragma unroll
        for (int s = 0; s < 2; s++) {
            bool v0ok = (Rt + s*16 + qr)     < nrows;
            bool v1ok = (Rt + s*16 + qr + 8) < nrows;
            #pragma unroll
            for (int i = 0; i < 3; i++) {
                float c[4] = { bi2[i][0], bi2[i][1], bi2[i][0], bi2[i][1] };
                mma8(c, a2[s][0], b2f[0][i]);
                mma8(c, a2[s][1], b2f[1][i]);
                mma8(c, a2[s][2], b2f[2][i]);
                if (v0ok) { aS0 += c[0] + c[1]; aA0 += fabsf(c[0]) + fabsf(c[1]); }
                if (v1ok) { aS1 += c[2] + c[3]; aA1 += fabsf(c[2]) + fabsf(c[3]); }
            }
        }

        // rotate triple buffers: computed slot becomes farthest prefetch target
        uint32_t td = dA; dA = dB; dB = dC; dC = td;
        const float* tf = fA; fA = fB; fB = fC; fC = tf;
    }
    asm volatile("cp.async.wait_group 0;" ::: "memory");   // drain tail prefetches

    // ---- CTA reduce ----
    float accS = aS0 + aS1, accA = aA0 + aA1;
    #pragma unroll
    for (int o = 16; o > 0; o >>= 1) {
        accS += __shfl_down_sync(0xFFFFFFFFu, accS, o);
        accA += __shfl_down_sync(0xFFFFFFFFu, accA, o);
    }
    if (lane == 0) { s_rs[wid] = (double)accS; s_ra[wid] = (double)accA; }
    __syncthreads();

    if (t == 0) {
        double S = s_rs[0] + s_rs[1] + s_rs[2] + s_rs[3];
        double A = s_ra[0] + s_ra[1] + s_ra[2] + s_ra[3];
        g_psum[blockIdx.x] = S;
        g_pabs[blockIdx.x] = A;
        __threadfence();
        unsigned v = atomicAdd(&g_done, 1u);
        s_last = (v == gridDim.x - 1) ? 1 : 0;
    }
    __syncthreads();

    // ---- last CTA: global reduce + exact halving count + write scalar ----
    if (s_last) {
        __threadfence();
        double S = 0.0, A = 0.0;
        for (int i = t; i < (int)gridDim.x; i += TPB) { S += g_psum[i]; A += g_pabs[i]; }
        double* fsum = (double*)sXb;           // mainloop done: overlay X buffers
        double* fabs_ = fsum + TPB;
        fsum[t] = S; fabs_[t] = A;
        __syncthreads();
        for (int o = TPB/2; o > 0; o >>= 1) {
            if (t < o) { fsum[t] += fsum[t + o]; fabs_[t] += fabs_[t + o]; }
            __syncthreads();
        }
        if (t == 0) {
            float s = (float)fabs_[0];
            int k = 0;
            while (s > 1.0f && k < 300) { s *= 0.5f; k++; }
            out[0] = (float)ldexp(fsum[0], -k);   // sum(h) * 2^-k (exact scale)
            __threadfence();
            g_done = 0;                            // reset for next graph replay
        }
    }
}

// ---------------- launch ----------------
extern "C" void kernel_launch(void* const* d_in, const int* in_sizes, int n_in,
                              void* d_out, int out_size) {
    const float* X  = (const float*)d_in[0];
    const float* W  = (const float*)d_in[1];
    const float* b  = (const float*)d_in[2];
    const float* Wi = (const float*)d_in[3];

    long long nrows = (long long)in_sizes[0] / DD;

    fused_kernel<<<NCTA, TPB>>>(X, W, b, Wi, nrows, (float*)d_out);
}